// round 14
// baseline (speedup 1.0000x reference)
#include <cuda_runtime.h>
#include <cuda_bf16.h>
#include <math_constants.h>

// Problem: cummax along axis=2 of x[B=8, Tt=128, Ts=128, C=512] fp32.
// out[b,t,j,c] = max_{j'<=j} x[b,t,j',c]
//
// R13: phase-batched R/W via asm-volatile ordering. Champion geometry
// (1024 CTAs x 128 threads, one (b,t) row per CTA) but each batch of 8
// j-steps is forced into: 8 back-to-back ld.global.v4 (independent ->
// MLP=8, pinned by program order) -> register max chain -> 8 back-to-back
// st.global.v4. Gives the DRAM scheduler long same-direction bursts per
// warp (R/W turnaround hypothesis), WITHOUT the smem/sync/single-thread
// machinery that sank R10/R11. ptxas cannot re-interleave ld/st pairs
// (volatile pins order), so the batch exists in SASS (regs ~48+).

constexpr int THREADS = 128;
constexpr int TS      = 128;
constexpr int C4      = 128;   // 512 channels / 4 floats
constexpr int JB      = 8;     // batch depth
constexpr int NB      = TS / JB;

__global__ void __launch_bounds__(THREADS) cummax_kernel(
    const float4* __restrict__ in, float4* __restrict__ out)
{
    const int bt = blockIdx.x;            // (b,t) row, 0..1023
    const int c4 = threadIdx.x;           // float4 within C, 0..127

    const float4* __restrict__ p = in  + (size_t)bt * TS * C4 + c4;
    float4* __restrict__       q = out + (size_t)bt * TS * C4 + c4;

    float mx = -CUDART_INF_F, my = -CUDART_INF_F,
          mz = -CUDART_INF_F, mw = -CUDART_INF_F;

    #pragma unroll 1
    for (int b = 0; b < NB; ++b) {
        const float4* pb = p + (size_t)(b * JB) * C4;
        float4*       qb = q + (size_t)(b * JB) * C4;

        float v[JB][4];

        // Phase 1: 8 independent loads, order pinned -> back-to-back LDG.128.
        #pragma unroll
        for (int u = 0; u < JB; ++u) {
            asm volatile("ld.global.v4.f32 {%0,%1,%2,%3}, [%4];"
                         : "=f"(v[u][0]), "=f"(v[u][1]),
                           "=f"(v[u][2]), "=f"(v[u][3])
                         : "l"(pb + (size_t)u * C4));
        }

        // Phase 2: serial prefix max in registers.
        #pragma unroll
        for (int u = 0; u < JB; ++u) {
            mx = fmaxf(mx, v[u][0]);
            my = fmaxf(my, v[u][1]);
            mz = fmaxf(mz, v[u][2]);
            mw = fmaxf(mw, v[u][3]);
            v[u][0] = mx; v[u][1] = my; v[u][2] = mz; v[u][3] = mw;
        }

        // Phase 3: 8 stores, order pinned -> back-to-back STG.128 burst.
        #pragma unroll
        for (int u = 0; u < JB; ++u) {
            asm volatile("st.global.v4.f32 [%0], {%1,%2,%3,%4};"
                         :: "l"(qb + (size_t)u * C4),
                            "f"(v[u][0]), "f"(v[u][1]),
                            "f"(v[u][2]), "f"(v[u][3])
                         : "memory");
        }
    }
}

extern "C" void kernel_launch(void* const* d_in, const int* in_sizes, int n_in,
                              void* d_out, int out_size)
{
    const float4* x = (const float4*)d_in[0];
    float4* y = (float4*)d_out;

    // 1024 CTAs = B*Tt rows; 128 threads = C/4 float4 columns per row.
    cummax_kernel<<<1024, THREADS>>>(x, y);
}